// round 5
// baseline (speedup 1.0000x reference)
#include <cuda_runtime.h>
#include <cuda_fp16.h>
#include <cstdint>
#include <math.h>

// Problem constants
#define Lc 2
#define Bc 4
#define Tc 1024
#define Dc 256
#define Hc 4
#define Mc 1024
#define NROWS (Bc*Tc)      // 4096
#define HD (Hc*Dc)         // 1024
#define LN_EPS 1e-5f

// ---------------------------------------------------------------------------
// Scratch (device globals; allocation-free contract)
// ---------------------------------------------------------------------------
__device__ float  g_x[NROWS*Dc];
__device__ float  g_proj[NROWS*Dc];
__device__ float  g_s[(long)Bc*Hc*Tc*Tc];      // fp32 attention scores (64MB)
__device__ __half g_xh[NROWS*Dc];
__device__ __half g_qh[NROWS*HD];
__device__ __half g_kh[NROWS*HD];
__device__ __half g_vh[NROWS*HD];
__device__ __half g_aoh[NROWS*HD];
__device__ __half g_hh[NROWS*Mc];
__device__ __half g_ph[(long)Bc*Hc*Tc*Tc];     // half probs (32MB)
__device__ __half g_wqh[Lc*Dc*HD];
__device__ __half g_wkh[Lc*Dc*HD];
__device__ __half g_wvh[Lc*Dc*HD];
__device__ __half g_woh[Lc*HD*Dc];
__device__ __half g_w1h[Lc*Dc*Mc];
__device__ __half g_w2h[Lc*Mc*Dc];

// ---------------------------------------------------------------------------
// Helpers
// ---------------------------------------------------------------------------
__device__ __forceinline__ uint32_t smem_u32(const void* p) {
    uint32_t a;
    asm("{ .reg .u64 t; cvta.to.shared.u64 t, %1; cvt.u32.u64 %0, t; }"
        : "=r"(a) : "l"(p));
    return a;
}
__device__ __forceinline__ void cp16(uint32_t dst, const void* src) {
    asm volatile("cp.async.cg.shared.global [%0], [%1], 16;"
                 :: "r"(dst), "l"(src) : "memory");
}
#define CP_COMMIT() asm volatile("cp.async.commit_group;" ::: "memory")
#define CP_WAIT(n)  asm volatile("cp.async.wait_group %0;" :: "n"(n) : "memory")

#define LDSM4(r, addr) \
    asm volatile("ldmatrix.sync.aligned.m8n8.x4.shared.b16 {%0,%1,%2,%3}, [%4];" \
        : "=r"((r)[0]), "=r"((r)[1]), "=r"((r)[2]), "=r"((r)[3]) : "r"(addr))
#define LDSM4T(r, addr) \
    asm volatile("ldmatrix.sync.aligned.m8n8.x4.trans.shared.b16 {%0,%1,%2,%3}, [%4];" \
        : "=r"((r)[0]), "=r"((r)[1]), "=r"((r)[2]), "=r"((r)[3]) : "r"(addr))

__device__ __forceinline__ void mma_f16(float* c, const uint32_t* a,
                                        uint32_t b0, uint32_t b1) {
    asm volatile(
        "mma.sync.aligned.m16n8k16.row.col.f32.f16.f16.f32 "
        "{%0,%1,%2,%3}, {%4,%5,%6,%7}, {%8,%9}, {%0,%1,%2,%3};"
        : "+f"(c[0]), "+f"(c[1]), "+f"(c[2]), "+f"(c[3])
        : "r"(a[0]), "r"(a[1]), "r"(a[2]), "r"(a[3]), "r"(b0), "r"(b1));
}

// ---------------------------------------------------------------------------
// fp16 mma GEMM, 3-stage cp.async pipeline, single barrier per K-chunk.
//   MT = CTA rows (64 or 128), CTA cols 128. BK=32. 8 warps.
//   TB=false: B is [N,K] K-major -> ldmatrix
//   TB=true : B is [K,N] N-major -> ldmatrix.trans
// flags bit1 = ReLU. Cf (fp32) / Ch (half) outputs, either may be null.
// Batch via blockIdx.z with split strides (z = zq*zdiv + zr).
// SMEM padded strides: A/Bnk rows 80B, Bkn rows 272B.
// ---------------------------------------------------------------------------
#define BSZ 10240
template<int MT, bool TB>
__global__ void __launch_bounds__(256, 2) gemm_h(
    const __half* __restrict__ A, const __half* __restrict__ B,
    float* __restrict__ Cf, __half* __restrict__ Ch, const float* __restrict__ bias,
    int K, int lda, int ldb, int ldc,
    long sA1, long sA2, long sB1, long sB2, long sC1, long sC2,
    int zdiv, float alpha, int flags)
{
    constexpr int ASZ = MT * 80;        // bytes per A stage
    constexpr int STG = ASZ + BSZ;      // bytes per stage
    constexpr int NA  = (MT == 128) ? 2 : 1;
    constexpr int NPAIR = (MT == 128) ? 4 : 2;
    constexpr int NT  = NPAIR * 2;

    extern __shared__ char smem[];
    uint32_t sbase = smem_u32(smem);

    int z  = blockIdx.z;
    int zq = z / zdiv, zr = z % zdiv;
    A  += (long)zq * sA1 + (long)zr * sA2;
    B  += (long)zq * sB1 + (long)zr * sB2;
    if (Cf) Cf += (long)zq * sC1 + (long)zr * sC2;
    if (Ch) Ch += (long)zq * sC1 + (long)zr * sC2;

    int t    = threadIdx.x;
    int lane = t & 31, w = t >> 5;
    int rowBase = blockIdx.y * MT;
    int colBase = blockIdx.x * 128;

    // ---- loader mappings
    const __half* pA[2]; uint32_t sa[2];
    const __half* pB[2]; uint32_t sb[2];
    #pragma unroll
    for (int i = 0; i < NA; i++) {
        int idx = t + i * 256;
        int ar = idx >> 2, ac = idx & 3;
        pA[i] = A + (long)(rowBase + ar) * lda + ac * 8;
        sa[i] = (uint32_t)(ar * 80 + ac * 16);
    }
    #pragma unroll
    for (int i = 0; i < 2; i++) {
        int idx = t + i * 256;
        if (TB) {
            int kr = idx >> 4, nc = idx & 15;
            pB[i] = B + (long)kr * ldb + colBase + nc * 8;
            sb[i] = (uint32_t)(kr * 272 + nc * 16);
        } else {
            int br = idx >> 2, bc = idx & 3;
            pB[i] = B + (long)(colBase + br) * ldb + bc * 8;
            sb[i] = (uint32_t)(br * 80 + bc * 16);
        }
    }
    const long bAdv = TB ? 32L * ldb : 32L;

    int NC = K >> 5;

    // prologue: chunks 0,1 -> stages 0,1
    #pragma unroll
    for (int p = 0; p < 2; p++) {
        uint32_t base = sbase + p * STG;
        #pragma unroll
        for (int i = 0; i < NA; i++) cp16(base + sa[i], pA[i] + p * 32);
        #pragma unroll
        for (int i = 0; i < 2; i++)  cp16(base + ASZ + sb[i], pB[i] + p * bAdv);
        CP_COMMIT();
    }

    // ---- compute mapping
    int mb, nb;
    if (MT == 128) { mb = (w & 3) * 32; nb = (w >> 2) * 64; }
    else           { mb = (w & 1) * 32; nb = (w >> 1) * 32; }
    int g  = lane >> 3, lr = lane & 7;
    int qr = lane >> 2, cl = lane & 3;

    float acc[2][NT][4];
    #pragma unroll
    for (int i = 0; i < 2; i++)
        #pragma unroll
        for (int j = 0; j < NT; j++)
            #pragma unroll
            for (int u = 0; u < 4; u++) acc[i][j][u] = 0.0f;

    int st = 0;       // stage of chunk c
    int ld = 2;       // stage for chunk c+2
    for (int c = 0; c < NC; c++) {
        if (c + 1 < NC) { CP_WAIT(1); } else { CP_WAIT(0); }
        __syncthreads();   // chunk c resident; all warps done with stage `ld`

        if (c + 2 < NC) {
            uint32_t base = sbase + ld * STG;
            #pragma unroll
            for (int i = 0; i < NA; i++) cp16(base + sa[i], pA[i] + (c + 2) * 32);
            #pragma unroll
            for (int i = 0; i < 2; i++)  cp16(base + ASZ + sb[i], pB[i] + (c + 2) * bAdv);
            CP_COMMIT();
        }

        uint32_t As = sbase + st * STG;
        uint32_t Bs = As + ASZ;

        #pragma unroll
        for (int kk = 0; kk < 32; kk += 16) {
            uint32_t af[2][4];
            #pragma unroll
            for (int mt = 0; mt < 2; mt++) {
                uint32_t addr = As + (uint32_t)((mb + mt * 16 + (g & 1) * 8 + lr) * 80
                                                + ((g >> 1) * 8 + kk) * 2);
                LDSM4(af[mt], addr);
            }
            #pragma unroll
            for (int np = 0; np < NPAIR; np++) {
                uint32_t bf[4];
                if (TB) {
                    uint32_t addr = Bs + (uint32_t)((kk + (g & 1) * 8 + lr) * 272
                                                    + (nb + np * 16 + (g >> 1) * 8) * 2);
                    LDSM4T(bf, addr);
                } else {
                    uint32_t addr = Bs + (uint32_t)((nb + np * 16 + (g >> 1) * 8 + lr) * 80
                                                    + ((g & 1) * 8 + kk) * 2);
                    LDSM4(bf, addr);
                }
                mma_f16(acc[0][np * 2 + 0], af[0], bf[0], bf[1]);
                mma_f16(acc[0][np * 2 + 1], af[0], bf[2], bf[3]);
                mma_f16(acc[1][np * 2 + 0], af[1], bf[0], bf[1]);
                mma_f16(acc[1][np * 2 + 1], af[1], bf[2], bf[3]);
            }
        }
        st = (st == 2) ? 0 : st + 1;
        ld = (ld == 2) ? 0 : ld + 1;
    }

    // ---- epilogue
    #pragma unroll
    for (int mt = 0; mt < 2; mt++) {
        int r0 = rowBase + mb + mt * 16 + qr;
        #pragma unroll
        for (int nt = 0; nt < NT; nt++) {
            int c0 = colBase + nb + nt * 8 + cl * 2;
            float b0 = 0.0f, b1 = 0.0f;
            if (bias) { b0 = bias[c0]; b1 = bias[c0 + 1]; }
            float v0 = (acc[mt][nt][0] + b0) * alpha;
            float v1 = (acc[mt][nt][1] + b1) * alpha;
            float v2 = (acc[mt][nt][2] + b0) * alpha;
            float v3 = (acc[mt][nt][3] + b1) * alpha;
            if (flags & 2) {
                v0 = fmaxf(v0, 0.0f); v1 = fmaxf(v1, 0.0f);
                v2 = fmaxf(v2, 0.0f); v3 = fmaxf(v3, 0.0f);
            }
            if (Cf) {
                *(float2*)&Cf[(long)r0 * ldc + c0]       = make_float2(v0, v1);
                *(float2*)&Cf[(long)(r0 + 8) * ldc + c0] = make_float2(v2, v3);
            }
            if (Ch) {
                *(__half2*)&Ch[(long)r0 * ldc + c0]       = __floats2half2_rn(v0, v1);
                *(__half2*)&Ch[(long)(r0 + 8) * ldc + c0] = __floats2half2_rn(v2, v3);
            }
        }
    }
}

// ---------------------------------------------------------------------------
// One-shot fp32 -> fp16 for queries + all weights (both layers).
// Segments: [0,1024) blocks -> queries (1M elems)
//           [1024 + i*512, +512) -> weight tensor i (512K elems each)
// Each block converts 1024 elems (256 thr x 4).
// ---------------------------------------------------------------------------
__global__ void __launch_bounds__(256) cvt_all_k(
    const float* __restrict__ qf, __half* __restrict__ qh,
    const float* __restrict__ w0f, __half* __restrict__ w0h,
    const float* __restrict__ w1f, __half* __restrict__ w1h,
    const float* __restrict__ w2f, __half* __restrict__ w2h,
    const float* __restrict__ w3f, __half* __restrict__ w3h,
    const float* __restrict__ w4f, __half* __restrict__ w4h,
    const float* __restrict__ w5f, __half* __restrict__ w5h)
{
    const float* src; __half* dst; long off;
    int b = blockIdx.x;
    if (b < 1024) { src = qf; dst = qh; off = (long)b * 1024; }
    else {
        int i = (b - 1024) >> 9;
        int r = (b - 1024) & 511;
        const float* S[6] = {w0f, w1f, w2f, w3f, w4f, w5f};
        __half*      D[6] = {w0h, w1h, w2h, w3h, w4h, w5h};
        src = S[i]; dst = D[i]; off = (long)r * 1024;
    }
    long idx = off + threadIdx.x * 4;
    float4 v = *(const float4*)&src[idx];
    *(__half2*)&dst[idx]     = __floats2half2_rn(v.x, v.y);
    *(__half2*)&dst[idx + 2] = __floats2half2_rn(v.z, v.w);
}

// ---------------------------------------------------------------------------
// Row softmax, fp32 scores -> half probs. One block (256 thr) per row (Tc).
// ---------------------------------------------------------------------------
__global__ void __launch_bounds__(256) softmax_k(const float* __restrict__ S,
                                                 __half* __restrict__ P)
{
    const float* row = S + (long)blockIdx.x * Tc;
    __half* prow = P + (long)blockIdx.x * Tc;
    int t = threadIdx.x;
    float4 v = *(const float4*)&row[t * 4];

    __shared__ float red[8];

    float m = fmaxf(fmaxf(v.x, v.y), fmaxf(v.z, v.w));
    #pragma unroll
    for (int o = 16; o > 0; o >>= 1) m = fmaxf(m, __shfl_xor_sync(0xffffffffu, m, o));
    if ((t & 31) == 0) red[t >> 5] = m;
    __syncthreads();
    m = red[0];
    #pragma unroll
    for (int w = 1; w < 8; w++) m = fmaxf(m, red[w]);

    v.x = __expf(v.x - m); v.y = __expf(v.y - m);
    v.z = __expf(v.z - m); v.w = __expf(v.w - m);
    float s = v.x + v.y + v.z + v.w;
    #pragma unroll
    for (int o = 16; o > 0; o >>= 1) s += __shfl_xor_sync(0xffffffffu, s, o);
    __syncthreads();
    if ((t & 31) == 0) red[t >> 5] = s;
    __syncthreads();
    s = 0.0f;
    #pragma unroll
    for (int w = 0; w < 8; w++) s += red[w];

    float inv = 1.0f / s;
    *(__half2*)&prow[t * 4]     = __floats2half2_rn(v.x * inv, v.y * inv);
    *(__half2*)&prow[t * 4 + 2] = __floats2half2_rn(v.z * inv, v.w * inv);
}

// ---------------------------------------------------------------------------
// Fused residual + LayerNorm, dual fp32 + fp16 output
// ---------------------------------------------------------------------------
__global__ void __launch_bounds__(256) ln_k(
    const float* __restrict__ a, const float* __restrict__ res,
    const float* __restrict__ sg, const float* __restrict__ bg,
    float* __restrict__ outF, __half* __restrict__ outH)
{
    long r = blockIdx.x;
    int  t = threadIdx.x;
    float v = a[r * Dc + t] + res[r * Dc + t];

    __shared__ float red[8];

    float s = v;
    #pragma unroll
    for (int o = 16; o > 0; o >>= 1) s += __shfl_xor_sync(0xffffffffu, s, o);
    if ((t & 31) == 0) red[t >> 5] = s;
    __syncthreads();
    s = 0.0f;
    #pragma unroll
    for (int w = 0; w < 8; w++) s += red[w];
    float mean = s * (1.0f / Dc);

    float d = v - mean;
    float q = d * d;
    #pragma unroll
    for (int o = 16; o > 0; o >>= 1) q += __shfl_xor_sync(0xffffffffu, q, o);
    __syncthreads();
    if ((t & 31) == 0) red[t >> 5] = q;
    __syncthreads();
    q = 0.0f;
    #pragma unroll
    for (int w = 0; w < 8; w++) q += red[w];
    float var = q * (1.0f / Dc);

    float o = d * rsqrtf(var + LN_EPS) * sg[t] + bg[t];
    outF[r * Dc + t] = o;
    outH[r * Dc + t] = __float2half_rn(o);
}

// ---------------------------------------------------------------------------
// Launch
// ---------------------------------------------------------------------------
extern "C" void kernel_launch(void* const* d_in, const int* in_sizes, int n_in,
                              void* d_out, int out_size)
{
    const float* queries = (const float*)d_in[0];
    const float* Wq   = (const float*)d_in[1];
    const float* bq   = (const float*)d_in[2];
    const float* Wk   = (const float*)d_in[3];
    const float* bk   = (const float*)d_in[4];
    const float* Wv   = (const float*)d_in[5];
    const float* bv   = (const float*)d_in[6];
    const float* Wo   = (const float*)d_in[7];
    const float* bo   = (const float*)d_in[8];
    const float* ln1s = (const float*)d_in[9];
    const float* ln1b = (const float*)d_in[10];
    const float* W1   = (const float*)d_in[11];
    const float* b1   = (const float*)d_in[12];
    const float* W2   = (const float*)d_in[13];
    const float* b2   = (const float*)d_in[14];
    const float* ln2s = (const float*)d_in[15];
    const float* ln2b = (const float*)d_in[16];

    float *x, *proj, *sc;
    __half *xh, *qh, *kh, *vh, *aoh, *hh, *ph;
    __half *wqh, *wkh, *wvh, *woh, *w1h, *w2h;
    cudaGetSymbolAddress((void**)&x,    g_x);
    cudaGetSymbolAddress((void**)&proj, g_proj);
    cudaGetSymbolAddress((void**)&sc,   g_s);
    cudaGetSymbolAddress((void**)&xh,   g_xh);
    cudaGetSymbolAddress((void**)&qh,   g_qh);
    cudaGetSymbolAddress((void**)&kh,   g_kh);
    cudaGetSymbolAddress((void**)&vh,   g_vh);
    cudaGetSymbolAddress((void**)&aoh,  g_aoh);
    cudaGetSymbolAddress((void**)&hh,   g_hh);
    cudaGetSymbolAddress((void**)&ph,   g_ph);
    cudaGetSymbolAddress((void**)&wqh,  g_wqh);
    cudaGetSymbolAddress((void**)&wkh,  g_wkh);
    cudaGetSymbolAddress((void**)&wvh,  g_wvh);
    cudaGetSymbolAddress((void**)&woh,  g_woh);
    cudaGetSymbolAddress((void**)&w1h,  g_w1h);
    cudaGetSymbolAddress((void**)&w2h,  g_w2h);

    const int SM128 = 3 * (128 * 80 + BSZ);  // 61440
    const int SM64  = 3 * (64 * 80 + BSZ);   // 46080
    cudaFuncSetAttribute(gemm_h<128,true>,  cudaFuncAttributeMaxDynamicSharedMemorySize, SM128);
    cudaFuncSetAttribute(gemm_h<128,false>, cudaFuncAttributeMaxDynamicSharedMemorySize, SM128);
    cudaFuncSetAttribute(gemm_h<64,true>,   cudaFuncAttributeMaxDynamicSharedMemorySize, SM64);

    const float* xin = queries;
    const float qscale = 1.0f / 16.0f;

    // All fp32->fp16 conversions in one kernel (queries + both layers' weights)
    cvt_all_k<<<1024 + 6 * 512, 256>>>(
        queries, xh, Wq, wqh, Wk, wkh, Wv, wvh, Wo, woh, W1, w1h, W2, w2h);

    for (int l = 0; l < Lc; l++) {
        const __half* wq = wqh + (long)l * Dc * HD;
        const __half* wk = wkh + (long)l * Dc * HD;
        const __half* wv = wvh + (long)l * Dc * HD;
        const __half* wo = woh + (long)l * HD * Dc;
        const __half* w1 = w1h + (long)l * Dc * Mc;
        const __half* w2 = w2h + (long)l * Mc * Dc;
        const float* bql = bq + (long)l * HD;
        const float* bkl = bk + (long)l * HD;
        const float* bvl = bv + (long)l * HD;
        const float* bol = bo + (long)l * Dc;
        const float* b1l = b1 + (long)l * Mc;
        const float* b2l = b2 + (long)l * Dc;
        const float* s1l = ln1s + (long)l * Dc;
        const float* o1l = ln1b + (long)l * Dc;
        const float* s2l = ln2s + (long)l * Dc;
        const float* o2l = ln2b + (long)l * Dc;

        // QKV projections: [4096,256] x [256,1024], B=[K,N]
        gemm_h<128,true><<<dim3(HD/128, NROWS/128, 1), 256, SM128>>>(
            xh, wq, nullptr, qh, bql, Dc, Dc, HD, HD,
            0,0,0,0,0,0, 1, qscale, 0);
        gemm_h<128,true><<<dim3(HD/128, NROWS/128, 1), 256, SM128>>>(
            xh, wk, nullptr, kh, bkl, Dc, Dc, HD, HD,
            0,0,0,0,0,0, 1, 1.0f, 0);
        gemm_h<128,true><<<dim3(HD/128, NROWS/128, 1), 256, SM128>>>(
            xh, wv, nullptr, vh, bvl, Dc, Dc, HD, HD,
            0,0,0,0,0,0, 1, 1.0f, 0);

        // scores[b,h] = q @ k^T  (B = K matrix, [N,K] K-major) -> fp32
        gemm_h<128,false><<<dim3(Tc/128, Tc/128, Bc*Hc), 256, SM128>>>(
            qh, kh, sc, nullptr, nullptr, Dc, HD, HD, Tc,
            (long)Tc*HD, (long)Dc,
            (long)Tc*HD, (long)Dc,
            (long)Hc*Tc*Tc, (long)Tc*Tc,
            Hc, 1.0f, 0);

        softmax_k<<<Bc*Hc*Tc, 256>>>(sc, ph);

        // out[b,:,h,:] = probs[b,h] @ V[b,h]  (V is [K=s, N=d], row stride HD)
        gemm_h<128,true><<<dim3(Dc/128, Tc/128, Bc*Hc), 256, SM128>>>(
            ph, vh, nullptr, aoh, nullptr, Tc, Tc, HD, HD,
            (long)Hc*Tc*Tc, (long)Tc*Tc,
            (long)Tc*HD, (long)Dc,
            (long)Tc*HD, (long)Dc,
            Hc, 1.0f, 0);

        // output projection: [4096,1024] x [1024,256] (64-row tiles: 128 CTAs)
        gemm_h<64,true><<<dim3(Dc/128, NROWS/64, 1), 256, SM64>>>(
            aoh, wo, proj, nullptr, bol, HD, HD, Dc, Dc,
            0,0,0,0,0,0, 1, 1.0f, 0);

        ln_k<<<NROWS, 256>>>(proj, xin, s1l, o1l, x, xh);

        // MLP
        gemm_h<128,true><<<dim3(Mc/128, NROWS/128, 1), 256, SM128>>>(
            xh, w1, nullptr, hh, b1l, Dc, Dc, Mc, Mc,
            0,0,0,0,0,0, 1, 1.0f, 2 /*ReLU*/);
        gemm_h<64,true><<<dim3(Dc/128, NROWS/64, 1), 256, SM64>>>(
            hh, w2, proj, nullptr, b2l, Mc, Mc, Dc, Dc,
            0,0,0,0,0,0, 1, 1.0f, 0);

        float* lnout = (l == Lc - 1) ? (float*)d_out : x;
        ln_k<<<NROWS, 256>>>(proj, x, s2l, o2l, lnout, xh);

        xin = x;
    }
}

// round 6
// speedup vs baseline: 1.4710x; 1.4710x over previous
#include <cuda_runtime.h>
#include <cuda_fp16.h>
#include <cstdint>
#include <math.h>

// Problem constants
#define Lc 2
#define Bc 4
#define Tc 1024
#define Dc 256
#define Hc 4
#define Mc 1024
#define NROWS (Bc*Tc)      // 4096
#define HD (Hc*Dc)         // 1024
#define LN_EPS 1e-5f

// ---------------------------------------------------------------------------
// Scratch (device globals; allocation-free contract)
// ---------------------------------------------------------------------------
__device__ float  g_x[NROWS*Dc];
__device__ float  g_proj[NROWS*Dc];
__device__ float  g_s[(long)Bc*Hc*Tc*Tc];      // fp32 attention scores (64MB)
__device__ float  g_bqkv[Lc*3*HD];             // packed QKV biases
__device__ __half g_xh[NROWS*Dc];
__device__ __half g_qkvh[3L*NROWS*HD];         // q | k | v contiguous
__device__ __half g_aoh[NROWS*HD];
__device__ __half g_hh[NROWS*Mc];
__device__ __half g_ph[(long)Bc*Hc*Tc*Tc];     // half probs (32MB)
__device__ __half g_wqkvh[Lc*3*Dc*HD];         // [l][q,k,v][D*HD]
__device__ __half g_woh[Lc*HD*Dc];
__device__ __half g_w1h[Lc*Dc*Mc];
__device__ __half g_w2h[Lc*Mc*Dc];

// ---------------------------------------------------------------------------
// Helpers
// ---------------------------------------------------------------------------
__device__ __forceinline__ uint32_t smem_u32(const void* p) {
    uint32_t a;
    asm("{ .reg .u64 t; cvta.to.shared.u64 t, %1; cvt.u32.u64 %0, t; }"
        : "=r"(a) : "l"(p));
    return a;
}
__device__ __forceinline__ void cp16(uint32_t dst, const void* src) {
    asm volatile("cp.async.cg.shared.global [%0], [%1], 16;"
                 :: "r"(dst), "l"(src) : "memory");
}
#define CP_COMMIT() asm volatile("cp.async.commit_group;" ::: "memory")
#define CP_WAIT(n)  asm volatile("cp.async.wait_group %0;" :: "n"(n) : "memory")

#define LDSM4(r, addr) \
    asm volatile("ldmatrix.sync.aligned.m8n8.x4.shared.b16 {%0,%1,%2,%3}, [%4];" \
        : "=r"((r)[0]), "=r"((r)[1]), "=r"((r)[2]), "=r"((r)[3]) : "r"(addr))
#define LDSM4T(r, addr) \
    asm volatile("ldmatrix.sync.aligned.m8n8.x4.trans.shared.b16 {%0,%1,%2,%3}, [%4];" \
        : "=r"((r)[0]), "=r"((r)[1]), "=r"((r)[2]), "=r"((r)[3]) : "r"(addr))

__device__ __forceinline__ void mma_f16(float* c, const uint32_t* a,
                                        uint32_t b0, uint32_t b1) {
    asm volatile(
        "mma.sync.aligned.m16n8k16.row.col.f32.f16.f16.f32 "
        "{%0,%1,%2,%3}, {%4,%5,%6,%7}, {%8,%9}, {%0,%1,%2,%3};"
        : "+f"(c[0]), "+f"(c[1]), "+f"(c[2]), "+f"(c[3])
        : "r"(a[0]), "r"(a[1]), "r"(a[2]), "r"(a[3]), "r"(b0), "r"(b1));
}

// ---------------------------------------------------------------------------
// fp16 mma GEMM (2-stage cp.async, Round-4 proven config).
//   MT = CTA rows (64 or 128), CTA cols 128. BK=32. 8 warps.
//   TB=false: B is [N,K] K-major -> ldmatrix
//   TB=true : B is [K,N] N-major -> ldmatrix.trans
// flags bit1 = ReLU. Cf (fp32) / Ch (half) outputs, either may be null.
// Batch via blockIdx.z: z = zq*zdiv + zr; per-operand split strides; bias
// advances by zq*sBias.
// SMEM padded strides: A/Bnk rows 80B, Bkn rows 272B.
// ---------------------------------------------------------------------------
#define BSZ 10240
template<int MT, bool TB>
__global__ void __launch_bounds__(256, 2) gemm_h(
    const __half* __restrict__ A, const __half* __restrict__ B,
    float* __restrict__ Cf, __half* __restrict__ Ch, const float* __restrict__ bias,
    int K, int lda, int ldb, int ldc,
    long sA1, long sA2, long sB1, long sB2, long sC1, long sC2, long sBias,
    int zdiv, float alpha, int flags)
{
    constexpr int ASZ = MT * 80;        // bytes per A stage
    constexpr int STG = ASZ + BSZ;      // bytes per stage
    constexpr int NA  = (MT == 128) ? 2 : 1;
    constexpr int NPAIR = (MT == 128) ? 4 : 2;
    constexpr int NT  = NPAIR * 2;

    extern __shared__ char smem[];
    uint32_t sbase = smem_u32(smem);

    int z  = blockIdx.z;
    int zq = z / zdiv, zr = z % zdiv;
    A  += (long)zq * sA1 + (long)zr * sA2;
    B  += (long)zq * sB1 + (long)zr * sB2;
    if (Cf)   Cf   += (long)zq * sC1 + (long)zr * sC2;
    if (Ch)   Ch   += (long)zq * sC1 + (long)zr * sC2;
    if (bias) bias += (long)zq * sBias;

    int t    = threadIdx.x;
    int lane = t & 31, w = t >> 5;
    int rowBase = blockIdx.y * MT;
    int colBase = blockIdx.x * 128;

    // ---- loader mappings
    const __half* pA[2]; uint32_t sa[2];
    const __half* pB[2]; uint32_t sb[2];
    #pragma unroll
    for (int i = 0; i < NA; i++) {
        int idx = t + i * 256;
        int ar = idx >> 2, ac = idx & 3;
        pA[i] = A + (long)(rowBase + ar) * lda + ac * 8;
        sa[i] = (uint32_t)(ar * 80 + ac * 16);
    }
    #pragma unroll
    for (int i = 0; i < 2; i++) {
        int idx = t + i * 256;
        if (TB) {
            int kr = idx >> 4, nc = idx & 15;
            pB[i] = B + (long)kr * ldb + colBase + nc * 8;
            sb[i] = (uint32_t)(kr * 272 + nc * 16);
        } else {
            int br = idx >> 2, bc = idx & 3;
            pB[i] = B + (long)(colBase + br) * ldb + bc * 8;
            sb[i] = (uint32_t)(br * 80 + bc * 16);
        }
    }
    const long bAdv = TB ? 32L * ldb : 32L;

    int NC = K >> 5;

    // prologue: stage 0 <- chunk 0
    {
        uint32_t base = sbase;
        #pragma unroll
        for (int i = 0; i < NA; i++) cp16(base + sa[i], pA[i]);
        #pragma unroll
        for (int i = 0; i < 2; i++)  cp16(base + ASZ + sb[i], pB[i]);
        CP_COMMIT();
    }

    // ---- compute mapping
    int mb, nb;
    if (MT == 128) { mb = (w & 3) * 32; nb = (w >> 2) * 64; }
    else           { mb = (w & 1) * 32; nb = (w >> 1) * 32; }
    int g  = lane >> 3, lr = lane & 7;
    int qr = lane >> 2, cl = lane & 3;

    float acc[2][NT][4];
    #pragma unroll
    for (int i = 0; i < 2; i++)
        #pragma unroll
        for (int j = 0; j < NT; j++)
            #pragma unroll
            for (int u = 0; u < 4; u++) acc[i][j][u] = 0.0f;

    for (int c = 0; c < NC; c++) {
        int st = c & 1;
        if (c + 1 < NC) {
            uint32_t base = sbase + ((c + 1) & 1) * STG;
            #pragma unroll
            for (int i = 0; i < NA; i++) cp16(base + sa[i], pA[i] + (c + 1) * 32);
            #pragma unroll
            for (int i = 0; i < 2; i++)  cp16(base + ASZ + sb[i], pB[i] + (c + 1) * bAdv);
            CP_COMMIT();
            CP_WAIT(1);
        } else {
            CP_WAIT(0);
        }
        __syncthreads();

        uint32_t As = sbase + st * STG;
        uint32_t Bs = As + ASZ;

        #pragma unroll
        for (int kk = 0; kk < 32; kk += 16) {
            uint32_t af[2][4];
            #pragma unroll
            for (int mt = 0; mt < 2; mt++) {
                uint32_t addr = As + (uint32_t)((mb + mt * 16 + (g & 1) * 8 + lr) * 80
                                                + ((g >> 1) * 8 + kk) * 2);
                LDSM4(af[mt], addr);
            }
            #pragma unroll
            for (int np = 0; np < NPAIR; np++) {
                uint32_t bf[4];
                if (TB) {
                    uint32_t addr = Bs + (uint32_t)((kk + (g & 1) * 8 + lr) * 272
                                                    + (nb + np * 16 + (g >> 1) * 8) * 2);
                    LDSM4T(bf, addr);
                } else {
                    uint32_t addr = Bs + (uint32_t)((nb + np * 16 + (g >> 1) * 8 + lr) * 80
                                                    + ((g & 1) * 8 + kk) * 2);
                    LDSM4(bf, addr);
                }
                mma_f16(acc[0][np * 2 + 0], af[0], bf[0], bf[1]);
                mma_f16(acc[0][np * 2 + 1], af[0], bf[2], bf[3]);
                mma_f16(acc[1][np * 2 + 0], af[1], bf[0], bf[1]);
                mma_f16(acc[1][np * 2 + 1], af[1], bf[2], bf[3]);
            }
        }
        __syncthreads();
    }

    // ---- epilogue
    #pragma unroll
    for (int mt = 0; mt < 2; mt++) {
        int r0 = rowBase + mb + mt * 16 + qr;
        #pragma unroll
        for (int nt = 0; nt < NT; nt++) {
            int c0 = colBase + nb + nt * 8 + cl * 2;
            float b0 = 0.0f, b1 = 0.0f;
            if (bias) { b0 = bias[c0]; b1 = bias[c0 + 1]; }
            float v0 = (acc[mt][nt][0] + b0) * alpha;
            float v1 = (acc[mt][nt][1] + b1) * alpha;
            float v2 = (acc[mt][nt][2] + b0) * alpha;
            float v3 = (acc[mt][nt][3] + b1) * alpha;
            if (flags & 2) {
                v0 = fmaxf(v0, 0.0f); v1 = fmaxf(v1, 0.0f);
                v2 = fmaxf(v2, 0.0f); v3 = fmaxf(v3, 0.0f);
            }
            if (Cf) {
                *(float2*)&Cf[(long)r0 * ldc + c0]       = make_float2(v0, v1);
                *(float2*)&Cf[(long)(r0 + 8) * ldc + c0] = make_float2(v2, v3);
            }
            if (Ch) {
                *(__half2*)&Ch[(long)r0 * ldc + c0]       = __floats2half2_rn(v0, v1);
                *(__half2*)&Ch[(long)(r0 + 8) * ldc + c0] = __floats2half2_rn(v2, v3);
            }
        }
    }
}

// ---------------------------------------------------------------------------
// One-shot convert/pack kernel. Each block handles 1024 elems (256 thr x 4).
// Block ranges:
//   [0, 1024)          queries -> g_xh
//   [1024, 2560)       QKV weights -> g_wqkvh[l][t]   (6 tensors x 256 blocks)
//   [2560, 3072)       Wo flat (Lc*HD*Dc)
//   [3072, 3584)       W1 flat
//   [3584, 4096)       W2 flat
//   [4096, 4102)       QKV biases (fp32 copy) -> g_bqkv[l][t]
// ---------------------------------------------------------------------------
__global__ void __launch_bounds__(256) cvt_all_k(
    const float* __restrict__ qf,
    const float* __restrict__ Wq, const float* __restrict__ Wk,
    const float* __restrict__ Wv, const float* __restrict__ Wo,
    const float* __restrict__ W1, const float* __restrict__ W2,
    const float* __restrict__ bq, const float* __restrict__ bk,
    const float* __restrict__ bv)
{
    int b = blockIdx.x;
    int tid = threadIdx.x;

    if (b >= 4096) {  // bias pack (fp32 copy)
        int j = b - 4096;           // 0..5
        int l = j / 3, tt = j % 3;
        const float* src = (tt == 0 ? bq : tt == 1 ? bk : bv) + (long)l * HD;
        float* dst = g_bqkv + (long)(l * 3 + tt) * HD;
        *(float4*)&dst[tid * 4] = *(const float4*)&src[tid * 4];
        return;
    }

    const float* src; __half* dst; long off;
    if (b < 1024) {
        src = qf; dst = g_xh; off = (long)b * 1024;
    } else if (b < 2560) {
        int i = b - 1024;
        int j = i >> 8;             // tensor index 0..5 = (l*3+t)
        int r = i & 255;
        int l = j / 3, tt = j % 3;
        src = (tt == 0 ? Wq : tt == 1 ? Wk : Wv) + (long)l * Dc * HD;
        dst = g_wqkvh + (long)j * Dc * HD;
        off = (long)r * 1024;
    } else if (b < 3072) {
        src = Wo; dst = g_woh; off = (long)(b - 2560) * 1024;
    } else if (b < 3584) {
        src = W1; dst = g_w1h; off = (long)(b - 3072) * 1024;
    } else {
        src = W2; dst = g_w2h; off = (long)(b - 3584) * 1024;
    }
    long idx = off + tid * 4;
    float4 v = *(const float4*)&src[idx];
    *(__half2*)&dst[idx]     = __floats2half2_rn(v.x, v.y);
    *(__half2*)&dst[idx + 2] = __floats2half2_rn(v.z, v.w);
}

// ---------------------------------------------------------------------------
// Row softmax, fp32 scores -> half probs. One block (256 thr) per row (Tc).
// ---------------------------------------------------------------------------
__global__ void __launch_bounds__(256) softmax_k(const float* __restrict__ S,
                                                 __half* __restrict__ P)
{
    const float* row = S + (long)blockIdx.x * Tc;
    __half* prow = P + (long)blockIdx.x * Tc;
    int t = threadIdx.x;
    float4 v = *(const float4*)&row[t * 4];

    __shared__ float red[8];

    float m = fmaxf(fmaxf(v.x, v.y), fmaxf(v.z, v.w));
    #pragma unroll
    for (int o = 16; o > 0; o >>= 1) m = fmaxf(m, __shfl_xor_sync(0xffffffffu, m, o));
    if ((t & 31) == 0) red[t >> 5] = m;
    __syncthreads();
    m = red[0];
    #pragma unroll
    for (int w = 1; w < 8; w++) m = fmaxf(m, red[w]);

    v.x = __expf(v.x - m); v.y = __expf(v.y - m);
    v.z = __expf(v.z - m); v.w = __expf(v.w - m);
    float s = v.x + v.y + v.z + v.w;
    #pragma unroll
    for (int o = 16; o > 0; o >>= 1) s += __shfl_xor_sync(0xffffffffu, s, o);
    __syncthreads();
    if ((t & 31) == 0) red[t >> 5] = s;
    __syncthreads();
    s = 0.0f;
    #pragma unroll
    for (int w = 0; w < 8; w++) s += red[w];

    float inv = 1.0f / s;
    *(__half2*)&prow[t * 4]     = __floats2half2_rn(v.x * inv, v.y * inv);
    *(__half2*)&prow[t * 4 + 2] = __floats2half2_rn(v.z * inv, v.w * inv);
}

// ---------------------------------------------------------------------------
// Fused residual + LayerNorm, dual fp32 + fp16 output
// ---------------------------------------------------------------------------
__global__ void __launch_bounds__(256) ln_k(
    const float* __restrict__ a, const float* __restrict__ res,
    const float* __restrict__ sg, const float* __restrict__ bg,
    float* __restrict__ outF, __half* __restrict__ outH)
{
    long r = blockIdx.x;
    int  t = threadIdx.x;
    float v = a[r * Dc + t] + res[r * Dc + t];

    __shared__ float red[8];

    float s = v;
    #pragma unroll
    for (int o = 16; o > 0; o >>= 1) s += __shfl_xor_sync(0xffffffffu, s, o);
    if ((t & 31) == 0) red[t >> 5] = s;
    __syncthreads();
    s = 0.0f;
    #pragma unroll
    for (int w = 0; w < 8; w++) s += red[w];
    float mean = s * (1.0f / Dc);

    float d = v - mean;
    float q = d * d;
    #pragma unroll
    for (int o = 16; o > 0; o >>= 1) q += __shfl_xor_sync(0xffffffffu, q, o);
    __syncthreads();
    if ((t & 31) == 0) red[t >> 5] = q;
    __syncthreads();
    q = 0.0f;
    #pragma unroll
    for (int w = 0; w < 8; w++) q += red[w];
    float var = q * (1.0f / Dc);

    float o = d * rsqrtf(var + LN_EPS) * sg[t] + bg[t];
    outF[r * Dc + t] = o;
    outH[r * Dc + t] = __float2half_rn(o);
}

// ---------------------------------------------------------------------------
// Launch
// ---------------------------------------------------------------------------
extern "C" void kernel_launch(void* const* d_in, const int* in_sizes, int n_in,
                              void* d_out, int out_size)
{
    const float* queries = (const float*)d_in[0];
    const float* Wq   = (const float*)d_in[1];
    const float* bq   = (const float*)d_in[2];
    const float* Wk   = (const float*)d_in[3];
    const float* bk   = (const float*)d_in[4];
    const float* Wv   = (const float*)d_in[5];
    const float* bv   = (const float*)d_in[6];
    const float* Wo   = (const float*)d_in[7];
    const float* bo   = (const float*)d_in[8];
    const float* ln1s = (const float*)d_in[9];
    const float* ln1b = (const float*)d_in[10];
    const float* W1   = (const float*)d_in[11];
    const float* b1   = (const float*)d_in[12];
    const float* W2   = (const float*)d_in[13];
    const float* b2   = (const float*)d_in[14];
    const float* ln2s = (const float*)d_in[15];
    const float* ln2b = (const float*)d_in[16];

    float *x, *proj, *sc, *bqkv;
    __half *xh, *qkvh, *aoh, *hh, *ph;
    __half *wqkvh, *woh, *w1h, *w2h;
    cudaGetSymbolAddress((void**)&x,     g_x);
    cudaGetSymbolAddress((void**)&proj,  g_proj);
    cudaGetSymbolAddress((void**)&sc,    g_s);
    cudaGetSymbolAddress((void**)&bqkv,  g_bqkv);
    cudaGetSymbolAddress((void**)&xh,    g_xh);
    cudaGetSymbolAddress((void**)&qkvh,  g_qkvh);
    cudaGetSymbolAddress((void**)&aoh,   g_aoh);
    cudaGetSymbolAddress((void**)&hh,    g_hh);
    cudaGetSymbolAddress((void**)&ph,    g_ph);
    cudaGetSymbolAddress((void**)&wqkvh, g_wqkvh);
    cudaGetSymbolAddress((void**)&woh,   g_woh);
    cudaGetSymbolAddress((void**)&w1h,   g_w1h);
    cudaGetSymbolAddress((void**)&w2h,   g_w2h);

    const int SM128 = 2 * (128 * 80 + BSZ);  // 40960
    const int SM64  = 2 * (64 * 80 + BSZ);   // 30720

    const float* xin = queries;
    const float qscale = 1.0f / 16.0f;

    // All conversions + bias packing in one kernel
    cvt_all_k<<<4102, 256>>>(queries, Wq, Wk, Wv, Wo, W1, W2, bq, bk, bv);

    __half* qh = qkvh;
    __half* kh = qkvh + (long)NROWS * HD;
    __half* vh = qkvh + 2L * NROWS * HD;

    for (int l = 0; l < Lc; l++) {
        const __half* wqkv = wqkvh + (long)l * 3 * Dc * HD;
        const __half* wo = woh + (long)l * HD * Dc;
        const __half* w1 = w1h + (long)l * Dc * Mc;
        const __half* w2 = w2h + (long)l * Mc * Dc;
        const float* bql3 = bqkv + (long)l * 3 * HD;
        const float* bol = bo + (long)l * Dc;
        const float* b1l = b1 + (long)l * Mc;
        const float* b2l = b2 + (long)l * Dc;
        const float* s1l = ln1s + (long)l * Dc;
        const float* o1l = ln1b + (long)l * Dc;
        const float* s2l = ln2s + (long)l * Dc;
        const float* o2l = ln2b + (long)l * Dc;

        // Fused QKV: z in {0,1,2} picks weight slab / output slab / bias slab.
        // (1/sqrt(D) folded into the scores GEMM alpha below.)
        gemm_h<128,true><<<dim3(HD/128, NROWS/128, 3), 256, SM128>>>(
            xh, wqkv, nullptr, qkvh, bql3, Dc, Dc, HD, HD,
            0, 0, (long)Dc*HD, 0, (long)NROWS*HD, 0, (long)HD,
            1, 1.0f, 0);

        // scores[b,h] = (q @ k^T) * qscale  -> fp32
        gemm_h<128,false><<<dim3(Tc/128, Tc/128, Bc*Hc), 256, SM128>>>(
            qh, kh, sc, nullptr, nullptr, Dc, HD, HD, Tc,
            (long)Tc*HD, (long)Dc,
            (long)Tc*HD, (long)Dc,
            (long)Hc*Tc*Tc, (long)Tc*Tc, 0,
            Hc, qscale, 0);

        softmax_k<<<Bc*Hc*Tc, 256>>>(sc, ph);

        // out[b,:,h,:] = probs[b,h] @ V[b,h]  (V is [K=s, N=d], row stride HD)
        gemm_h<128,true><<<dim3(Dc/128, Tc/128, Bc*Hc), 256, SM128>>>(
            ph, vh, nullptr, aoh, nullptr, Tc, Tc, HD, HD,
            (long)Hc*Tc*Tc, (long)Tc*Tc,
            (long)Tc*HD, (long)Dc,
            (long)Tc*HD, (long)Dc, 0,
            Hc, 1.0f, 0);

        // output projection: [4096,1024] x [1024,256] (64-row tiles)
        gemm_h<64,true><<<dim3(Dc/128, NROWS/64, 1), 256, SM64>>>(
            aoh, wo, proj, nullptr, bol, HD, HD, Dc, Dc,
            0,0,0,0,0,0,0, 1, 1.0f, 0);

        ln_k<<<NROWS, 256>>>(proj, xin, s1l, o1l, x, xh);

        // MLP
        gemm_h<128,true><<<dim3(Mc/128, NROWS/128, 1), 256, SM128>>>(
            xh, w1, nullptr, hh, b1l, Dc, Dc, Mc, Mc,
            0,0,0,0,0,0,0, 1, 1.0f, 2 /*ReLU*/);
        gemm_h<64,true><<<dim3(Dc/128, NROWS/64, 1), 256, SM64>>>(
            hh, w2, proj, nullptr, b2l, Mc, Mc, Dc, Dc,
            0,0,0,0,0,0,0, 1, 1.0f, 0);

        float* lnout = (l == Lc - 1) ? (float*)d_out : x;
        ln_k<<<NROWS, 256>>>(proj, x, s2l, o2l, lnout, xh);

        xin = x;
    }
}